// round 1
// baseline (speedup 1.0000x reference)
#include <cuda_runtime.h>

#define BZ 32
#define MZ 8192
#define DZ 256
#define NCHUNK 16
#define TOKS (MZ / NCHUNK)          // 512 tokens per chunk
#define WARPS 8
#define TOKS_PER_WARP (TOKS / WARPS) // 64
#define ATTN_SCALE 0.0625f           // 1/sqrt(256)

// Scratch (no allocations allowed in kernel_launch)
__device__ float  g_qtil[BZ * DZ];                 // 32 KB
__device__ float  g_pacc[BZ * NCHUNK * DZ];        // 512 KB
__device__ float2 g_pmz[BZ * NCHUNK];              // (max, Z) per chunk

// ---------------------------------------------------------------------------
// Kernel A: q~[b,d] = SCALE * sum_j (q_w q + q_b)[j] * k_w[j,d]
// (the q . k_b constant term cancels in softmax and is dropped)
// ---------------------------------------------------------------------------
__global__ void __launch_bounds__(DZ) precompute_qtil(
    const float* __restrict__ query,
    const float* __restrict__ q_w,
    const float* __restrict__ q_b,
    const float* __restrict__ k_w)
{
    const int b = blockIdx.x;
    const int tid = threadIdx.x;

    __shared__ float q_s[DZ];
    __shared__ float qr_s[DZ];

    q_s[tid] = query[b * DZ + tid];
    __syncthreads();

    // q[j] = sum_i query[i] * q_w[j*D + i] + q_b[j]
    float acc = q_b[tid];
    const float* wrow = q_w + tid * DZ;
    #pragma unroll 8
    for (int i = 0; i < DZ; i++) acc += q_s[i] * wrow[i];
    qr_s[tid] = acc;
    __syncthreads();

    // qtil[d] = SCALE * sum_j q[j] * k_w[j*D + d]   (coalesced over d)
    float t = 0.0f;
    #pragma unroll 8
    for (int j = 0; j < DZ; j++) t += qr_s[j] * k_w[j * DZ + tid];
    g_qtil[b * DZ + tid] = t * ATTN_SCALE;
}

// ---------------------------------------------------------------------------
// Kernel B: single pass over tokens with online softmax.
// Block = (batch b, chunk c). 8 warps; each warp owns 64 consecutive tokens.
// Per token: lane loads 8 dims (2x float4), shuffle-reduced dot -> logit,
// lazy-rescale online softmax, accumulate p * token into per-lane acc.
// ---------------------------------------------------------------------------
__global__ void __launch_bounds__(256) attn_pass(const float* __restrict__ tokens)
{
    const int b    = blockIdx.x / NCHUNK;
    const int c    = blockIdx.x % NCHUNK;
    const int tid  = threadIdx.x;
    const int w    = tid >> 5;
    const int lane = tid & 31;

    const float4* qt = (const float4*)(g_qtil + b * DZ);
    const float4 qa = qt[lane];
    const float4 qb = qt[32 + lane];

    float  m = -1e30f, z = 0.0f;
    float4 aa = make_float4(0.f, 0.f, 0.f, 0.f);
    float4 ab = make_float4(0.f, 0.f, 0.f, 0.f);

    const int tok0 = c * TOKS + w * TOKS_PER_WARP;
    const float4* base = (const float4*)tokens + ((size_t)b * MZ + tok0) * (DZ / 4);

    #pragma unroll 2
    for (int t = 0; t < TOKS_PER_WARP; t++) {
        const float4* tp = base + (size_t)t * (DZ / 4);
        const float4 xa = tp[lane];
        const float4 xb = tp[32 + lane];

        float d = xa.x * qa.x + xa.y * qa.y + xa.z * qa.z + xa.w * qa.w
                + xb.x * qb.x + xb.y * qb.y + xb.z * qb.z + xb.w * qb.w;
        #pragma unroll
        for (int o = 16; o > 0; o >>= 1)
            d += __shfl_xor_sync(0xffffffffu, d, o);

        float p;
        if (d > m) {                       // warp-uniform branch (rare: ~log M)
            const float corr = __expf(m - d);
            z *= corr;
            aa.x *= corr; aa.y *= corr; aa.z *= corr; aa.w *= corr;
            ab.x *= corr; ab.y *= corr; ab.z *= corr; ab.w *= corr;
            m = d;
            p = 1.0f;
        } else {
            p = __expf(d - m);
        }
        z += p;
        aa.x += p * xa.x; aa.y += p * xa.y; aa.z += p * xa.z; aa.w += p * xa.w;
        ab.x += p * xb.x; ab.y += p * xb.y; ab.z += p * xb.z; ab.w += p * xb.w;
    }

    // Combine 8 warps within the block
    __shared__ float  sm_m[WARPS];
    __shared__ float  sm_z[WARPS];
    __shared__ float4 sm_acc[WARPS][64];   // [warp][256 floats]

    if (lane == 0) { sm_m[w] = m; sm_z[w] = z; }
    sm_acc[w][lane]      = aa;
    sm_acc[w][32 + lane] = ab;
    __syncthreads();

    float Ms = sm_m[0];
    #pragma unroll
    for (int i = 1; i < WARPS; i++) Ms = fmaxf(Ms, sm_m[i]);

    const float* sa = (const float*)sm_acc;   // [8][256]
    float accd = 0.0f;
    #pragma unroll
    for (int i = 0; i < WARPS; i++)
        accd += sa[i * DZ + tid] * __expf(sm_m[i] - Ms);
    g_pacc[(b * NCHUNK + c) * DZ + tid] = accd;

    if (tid == 0) {
        float zt = 0.0f;
        #pragma unroll
        for (int i = 0; i < WARPS; i++) zt += sm_z[i] * __expf(sm_m[i] - Ms);
        g_pmz[b * NCHUNK + c] = make_float2(Ms, zt);
    }
}

// ---------------------------------------------------------------------------
// Kernel C: merge chunk partials -> t[b,:], then out[b,j] = v_w[j,:].t + v_b[j]
// ---------------------------------------------------------------------------
__global__ void __launch_bounds__(256) finalize(
    const float* __restrict__ v_w,
    const float* __restrict__ v_b,
    float* __restrict__ out)
{
    const int b    = blockIdx.x;
    const int tid  = threadIdx.x;
    const int w    = tid >> 5;
    const int lane = tid & 31;

    __shared__ float  t_s[DZ];
    __shared__ float2 mz_s[NCHUNK];

    if (tid < NCHUNK) mz_s[tid] = g_pmz[b * NCHUNK + tid];
    __syncthreads();

    float Mg = mz_s[0].x;
    #pragma unroll
    for (int i = 1; i < NCHUNK; i++) Mg = fmaxf(Mg, mz_s[i].x);

    float sc[NCHUNK];
    float Zg = 0.0f;
    #pragma unroll
    for (int i = 0; i < NCHUNK; i++) {
        const float e = __expf(mz_s[i].x - Mg);
        sc[i] = e;
        Zg += mz_s[i].y * e;
    }
    const float inv = 1.0f / Zg;

    float td = 0.0f;
    #pragma unroll
    for (int i = 0; i < NCHUNK; i++)
        td += g_pacc[(b * NCHUNK + i) * DZ + tid] * sc[i];
    t_s[tid] = td * inv;
    __syncthreads();

    // Each warp computes 32 output dims; coalesced reads of v_w rows.
    for (int jj = 0; jj < 32; jj++) {
        const int j = w * 32 + jj;
        const float* row = v_w + j * DZ;
        float s = 0.0f;
        #pragma unroll
        for (int i = 0; i < 8; i++)
            s += row[i * 32 + lane] * t_s[i * 32 + lane];
        #pragma unroll
        for (int o = 16; o > 0; o >>= 1)
            s += __shfl_xor_sync(0xffffffffu, s, o);
        if (lane == 0) out[b * DZ + j] = s + v_b[j];
    }
}

// ---------------------------------------------------------------------------
// Inputs (metadata order): 0 query, 1 tokens, 2 q_w, 3 q_b, 4 k_w, 5 k_b,
//                          6 v_w, 7 v_b.  k_b is provably unused (softmax
//                          shift invariance).
// ---------------------------------------------------------------------------
extern "C" void kernel_launch(void* const* d_in, const int* in_sizes, int n_in,
                              void* d_out, int out_size)
{
    const float* query  = (const float*)d_in[0];
    const float* tokens = (const float*)d_in[1];
    const float* q_w    = (const float*)d_in[2];
    const float* q_b    = (const float*)d_in[3];
    const float* k_w    = (const float*)d_in[4];
    const float* v_w    = (const float*)d_in[6];
    const float* v_b    = (const float*)d_in[7];
    float* out = (float*)d_out;

    precompute_qtil<<<BZ, DZ>>>(query, q_w, q_b, k_w);
    attn_pass<<<BZ * NCHUNK, 256>>>(tokens);
    finalize<<<BZ, 256>>>(v_w, v_b, out);
}

// round 2
// speedup vs baseline: 2.5418x; 2.5418x over previous
#include <cuda_runtime.h>

#define BZ 32
#define MZ 8192
#define DZ 256
#define NCHUNK 32
#define TOKS (MZ / NCHUNK)            // 256 tokens per chunk
#define WARPS 8
#define TOKS_PER_WARP (TOKS / WARPS)  // 32
#define ATTN_SCALE 0.0625f            // 1/sqrt(256)

// Scratch (no allocations allowed in kernel_launch)
__device__ float  g_qtil[BZ * DZ];                 // 32 KB
__device__ float  g_pacc[BZ * NCHUNK * DZ];        // 1 MB
__device__ float2 g_pmz[BZ * NCHUNK];              // (max, Z) per chunk

#define DOT8(xa, xb) ((xa).x*qa.x + (xa).y*qa.y + (xa).z*qa.z + (xa).w*qa.w \
                    + (xb).x*qb.x + (xb).y*qb.y + (xb).z*qb.z + (xb).w*qb.w)

// ---------------------------------------------------------------------------
// Kernel A: q~[b,d] = SCALE * sum_j (q_w q + q_b)[j] * k_w[j,d]
// (the q . k_b constant term cancels in softmax and is dropped)
// Restructured for latency: warp-parallel split over j with batched ILP.
// ---------------------------------------------------------------------------
__global__ void __launch_bounds__(256) precompute_qtil(
    const float* __restrict__ query,
    const float* __restrict__ q_w,
    const float* __restrict__ q_b,
    const float* __restrict__ k_w)
{
    const int b    = blockIdx.x;
    const int tid  = threadIdx.x;
    const int w    = tid >> 5;
    const int lane = tid & 31;

    __shared__ float q_s[DZ];
    __shared__ float qr_s[DZ];
    __shared__ float part[WARPS][DZ];   // 8 KB

    q_s[tid] = query[b * DZ + tid];
    __syncthreads();

    const float4 qa = *(const float4*)(q_s + lane * 4);
    const float4 qb = *(const float4*)(q_s + 128 + lane * 4);

    // Phase 1: qr[j] = q_w[j,:] . q + q_b[j].  Warp w owns j in [32w, 32w+32),
    // processed in groups of 4 for ILP across the shuffle reductions.
    #pragma unroll
    for (int g = 0; g < 8; g++) {
        const int j0 = w * 32 + g * 4;
        const float4* r0 = (const float4*)(q_w + (size_t)(j0 + 0) * DZ);
        const float4* r1 = (const float4*)(q_w + (size_t)(j0 + 1) * DZ);
        const float4* r2 = (const float4*)(q_w + (size_t)(j0 + 2) * DZ);
        const float4* r3 = (const float4*)(q_w + (size_t)(j0 + 3) * DZ);
        const float4 a0 = r0[lane], b0 = r0[32 + lane];
        const float4 a1 = r1[lane], b1 = r1[32 + lane];
        const float4 a2 = r2[lane], b2 = r2[32 + lane];
        const float4 a3 = r3[lane], b3 = r3[32 + lane];
        float d0 = DOT8(a0, b0);
        float d1 = DOT8(a1, b1);
        float d2 = DOT8(a2, b2);
        float d3 = DOT8(a3, b3);
        #pragma unroll
        for (int o = 16; o > 0; o >>= 1) {
            d0 += __shfl_xor_sync(0xffffffffu, d0, o);
            d1 += __shfl_xor_sync(0xffffffffu, d1, o);
            d2 += __shfl_xor_sync(0xffffffffu, d2, o);
            d3 += __shfl_xor_sync(0xffffffffu, d3, o);
        }
        if (lane < 4) {
            const float v = (lane == 0) ? d0 : (lane == 1) ? d1 : (lane == 2) ? d2 : d3;
            qr_s[j0 + lane] = v + q_b[j0 + lane];
        }
    }
    __syncthreads();

    // Phase 2: qtil[d] = sum_j qr[j] * k_w[j,d].  Warp w accumulates its own
    // 32-j slice into register d-accumulators (independent loads -> full MLP).
    float4 pa = make_float4(0.f, 0.f, 0.f, 0.f);
    float4 pb = make_float4(0.f, 0.f, 0.f, 0.f);
    #pragma unroll 8
    for (int jj = 0; jj < 32; jj++) {
        const int j = w * 32 + jj;
        const float s = qr_s[j];
        const float4* row = (const float4*)(k_w + (size_t)j * DZ);
        const float4 xa = row[lane];
        const float4 xb = row[32 + lane];
        pa.x += s * xa.x; pa.y += s * xa.y; pa.z += s * xa.z; pa.w += s * xa.w;
        pb.x += s * xb.x; pb.y += s * xb.y; pb.z += s * xb.z; pb.w += s * xb.w;
    }
    *(float4*)(&part[w][lane * 4])       = pa;
    *(float4*)(&part[w][128 + lane * 4]) = pb;
    __syncthreads();

    float acc = 0.0f;
    #pragma unroll
    for (int i = 0; i < WARPS; i++) acc += part[i][tid];
    g_qtil[b * DZ + tid] = acc * ATTN_SCALE;
}

// ---------------------------------------------------------------------------
// Kernel B: single streaming pass with online softmax.
// Block = (batch, chunk), 1024 blocks. Each warp owns 32 consecutive tokens,
// processed in groups of 4 for load + shuffle-reduction ILP.
// ---------------------------------------------------------------------------
#define ONLINE_UPDATE(dt, xa, xb)                                          \
    do {                                                                   \
        float p;                                                           \
        if (dt > m) {                                                      \
            const float corr = __expf(m - dt);                             \
            z *= corr;                                                     \
            aa.x *= corr; aa.y *= corr; aa.z *= corr; aa.w *= corr;        \
            ab.x *= corr; ab.y *= corr; ab.z *= corr; ab.w *= corr;        \
            m = dt; p = 1.0f;                                              \
        } else {                                                           \
            p = __expf(dt - m);                                            \
        }                                                                  \
        z += p;                                                            \
        aa.x += p * (xa).x; aa.y += p * (xa).y;                            \
        aa.z += p * (xa).z; aa.w += p * (xa).w;                            \
        ab.x += p * (xb).x; ab.y += p * (xb).y;                            \
        ab.z += p * (xb).z; ab.w += p * (xb).w;                            \
    } while (0)

__global__ void __launch_bounds__(256) attn_pass(const float* __restrict__ tokens)
{
    const int b    = blockIdx.x >> 5;     // / NCHUNK
    const int c    = blockIdx.x & 31;     // % NCHUNK
    const int tid  = threadIdx.x;
    const int w    = tid >> 5;
    const int lane = tid & 31;

    const float4* qt = (const float4*)(g_qtil + b * DZ);
    const float4 qa = qt[lane];
    const float4 qb = qt[32 + lane];

    float  m = -1e30f, z = 0.0f;
    float4 aa = make_float4(0.f, 0.f, 0.f, 0.f);
    float4 ab = make_float4(0.f, 0.f, 0.f, 0.f);

    const int tok0 = c * TOKS + w * TOKS_PER_WARP;
    const float4* base = (const float4*)tokens + ((size_t)b * MZ + tok0) * (DZ / 4);

    #pragma unroll 2
    for (int g = 0; g < TOKS_PER_WARP / 4; g++) {
        const float4* tp = base + (size_t)g * 4 * (DZ / 4);
        // 8 independent streaming loads (4 tokens x 2 float4)
        const float4 xa0 = __ldcs(tp + lane);
        const float4 xb0 = __ldcs(tp + 32 + lane);
        const float4 xa1 = __ldcs(tp + 64 + lane);
        const float4 xb1 = __ldcs(tp + 96 + lane);
        const float4 xa2 = __ldcs(tp + 128 + lane);
        const float4 xb2 = __ldcs(tp + 160 + lane);
        const float4 xa3 = __ldcs(tp + 192 + lane);
        const float4 xb3 = __ldcs(tp + 224 + lane);

        float d0 = DOT8(xa0, xb0);
        float d1 = DOT8(xa1, xb1);
        float d2 = DOT8(xa2, xb2);
        float d3 = DOT8(xa3, xb3);
        #pragma unroll
        for (int o = 16; o > 0; o >>= 1) {
            d0 += __shfl_xor_sync(0xffffffffu, d0, o);
            d1 += __shfl_xor_sync(0xffffffffu, d1, o);
            d2 += __shfl_xor_sync(0xffffffffu, d2, o);
            d3 += __shfl_xor_sync(0xffffffffu, d3, o);
        }
        ONLINE_UPDATE(d0, xa0, xb0);
        ONLINE_UPDATE(d1, xa1, xb1);
        ONLINE_UPDATE(d2, xa2, xb2);
        ONLINE_UPDATE(d3, xa3, xb3);
    }

    // Combine 8 warps within the block
    __shared__ float  sm_m[WARPS];
    __shared__ float  sm_z[WARPS];
    __shared__ float4 sm_acc[WARPS][64];   // [warp][256 floats]

    if (lane == 0) { sm_m[w] = m; sm_z[w] = z; }
    sm_acc[w][lane]      = aa;
    sm_acc[w][32 + lane] = ab;
    __syncthreads();

    float Ms = sm_m[0];
    #pragma unroll
    for (int i = 1; i < WARPS; i++) Ms = fmaxf(Ms, sm_m[i]);

    const float* sa = (const float*)sm_acc;   // [8][256]
    float accd = 0.0f;
    #pragma unroll
    for (int i = 0; i < WARPS; i++)
        accd += sa[i * DZ + tid] * __expf(sm_m[i] - Ms);
    g_pacc[(b * NCHUNK + c) * DZ + tid] = accd;

    if (tid == 0) {
        float zt = 0.0f;
        #pragma unroll
        for (int i = 0; i < WARPS; i++) zt += sm_z[i] * __expf(sm_m[i] - Ms);
        g_pmz[b * NCHUNK + c] = make_float2(Ms, zt);
    }
}

// ---------------------------------------------------------------------------
// Kernel C: merge chunk partials -> t[b,:], then out[b,j] = v_w[j,:].t + v_b[j]
// ---------------------------------------------------------------------------
__global__ void __launch_bounds__(256) finalize(
    const float* __restrict__ v_w,
    const float* __restrict__ v_b,
    float* __restrict__ out)
{
    const int b    = blockIdx.x;
    const int tid  = threadIdx.x;
    const int w    = tid >> 5;
    const int lane = tid & 31;

    __shared__ float  t_s[DZ];
    __shared__ float2 mz_s[NCHUNK];

    if (tid < NCHUNK) mz_s[tid] = g_pmz[b * NCHUNK + tid];
    __syncthreads();

    float Mg = mz_s[0].x;
    #pragma unroll
    for (int i = 1; i < NCHUNK; i++) Mg = fmaxf(Mg, mz_s[i].x);

    float Zg = 0.0f;
    #pragma unroll
    for (int i = 0; i < NCHUNK; i++) Zg += mz_s[i].y * __expf(mz_s[i].x - Mg);
    const float inv = 1.0f / Zg;

    float td = 0.0f;
    #pragma unroll 8
    for (int i = 0; i < NCHUNK; i++)
        td += g_pacc[(b * NCHUNK + i) * DZ + tid] * __expf(mz_s[i].x - Mg);
    t_s[tid] = td * inv;
    __syncthreads();

    const float4 qa = *(const float4*)(t_s + lane * 4);          // t chunks
    const float4 qb = *(const float4*)(t_s + 128 + lane * 4);

    // Warp w computes outputs j in [32w, 32w+32) in ILP groups of 4.
    #pragma unroll
    for (int g = 0; g < 8; g++) {
        const int j0 = w * 32 + g * 4;
        const float4* r0 = (const float4*)(v_w + (size_t)(j0 + 0) * DZ);
        const float4* r1 = (const float4*)(v_w + (size_t)(j0 + 1) * DZ);
        const float4* r2 = (const float4*)(v_w + (size_t)(j0 + 2) * DZ);
        const float4* r3 = (const float4*)(v_w + (size_t)(j0 + 3) * DZ);
        const float4 a0 = r0[lane], b0 = r0[32 + lane];
        const float4 a1 = r1[lane], b1 = r1[32 + lane];
        const float4 a2 = r2[lane], b2 = r2[32 + lane];
        const float4 a3 = r3[lane], b3 = r3[32 + lane];
        float d0 = DOT8(a0, b0);
        float d1 = DOT8(a1, b1);
        float d2 = DOT8(a2, b2);
        float d3 = DOT8(a3, b3);
        #pragma unroll
        for (int o = 16; o > 0; o >>= 1) {
            d0 += __shfl_xor_sync(0xffffffffu, d0, o);
            d1 += __shfl_xor_sync(0xffffffffu, d1, o);
            d2 += __shfl_xor_sync(0xffffffffu, d2, o);
            d3 += __shfl_xor_sync(0xffffffffu, d3, o);
        }
        if (lane < 4) {
            const float v = (lane == 0) ? d0 : (lane == 1) ? d1 : (lane == 2) ? d2 : d3;
            out[b * DZ + j0 + lane] = v + v_b[j0 + lane];
        }
    }
}

// ---------------------------------------------------------------------------
// Inputs (metadata order): 0 query, 1 tokens, 2 q_w, 3 q_b, 4 k_w, 5 k_b,
//                          6 v_w, 7 v_b.  k_b is provably unused (softmax
//                          shift invariance).
// ---------------------------------------------------------------------------
extern "C" void kernel_launch(void* const* d_in, const int* in_sizes, int n_in,
                              void* d_out, int out_size)
{
    const float* query  = (const float*)d_in[0];
    const float* tokens = (const float*)d_in[1];
    const float* q_w    = (const float*)d_in[2];
    const float* q_b    = (const float*)d_in[3];
    const float* k_w    = (const float*)d_in[4];
    const float* v_w    = (const float*)d_in[6];
    const float* v_b    = (const float*)d_in[7];
    float* out = (float*)d_out;

    precompute_qtil<<<BZ, 256>>>(query, q_w, q_b, k_w);
    attn_pass<<<BZ * NCHUNK, 256>>>(tokens);
    finalize<<<BZ, 256>>>(v_w, v_b, out);
}

// round 4
// speedup vs baseline: 3.0244x; 1.1899x over previous
#include <cuda_runtime.h>

#define BZ 32
#define MZ 8192
#define DZ 256
#define NCHUNK 32
#define TOKS (MZ / NCHUNK)            // 256 tokens per chunk
#define WARPS 8
#define TOKS_PER_WARP (TOKS / WARPS)  // 32
#define NSLICE 8                      // j-slices for kernels A and C
#define ATTN_SCALE 0.0625f            // 1/sqrt(256)

// Scratch (no allocations allowed in kernel_launch)
__device__ float  g_part[BZ * NSLICE * DZ];        // qtil partials, 256 KB
__device__ float  g_pacc[BZ * NCHUNK * DZ];        // 1 MB
__device__ float2 g_pmz[BZ * NCHUNK];              // (max, Z) per chunk

#define DOT8(xa, xb) ((xa).x*qa.x + (xa).y*qa.y + (xa).z*qa.z + (xa).w*qa.w \
                    + (xb).x*qb.x + (xb).y*qb.y + (xb).z*qb.z + (xb).w*qb.w)

// ---------------------------------------------------------------------------
// Kernel A: partial q~ per (batch, j-slice).  Block (b,s), 256 blocks.
// Warp w owns j in [32s + 4w, 32s + 4w + 4):
//   phase 1 (warp-local): qr[j] = q_w[j,:].query[b] + q_b[j]
//   phase 2 (warp-local): part_d += sum_j qr[j] * k_w[j,d]
// then one block reduce over the 8 warps -> g_part[b][s][:].
// (the q . k_b constant cancels in softmax and is dropped; SCALE applied in B)
// ---------------------------------------------------------------------------
__global__ void __launch_bounds__(256) qtil_partial(
    const float* __restrict__ query,
    const float* __restrict__ q_w,
    const float* __restrict__ q_b,
    const float* __restrict__ k_w)
{
    const int b    = blockIdx.x >> 3;
    const int s    = blockIdx.x & 7;
    const int tid  = threadIdx.x;
    const int w    = tid >> 5;
    const int lane = tid & 31;

    __shared__ float part[WARPS][DZ];   // 8 KB

    const float4* qv = (const float4*)(query + (size_t)b * DZ);
    const float4 qa = qv[lane];          // query dims [4*lane, 4*lane+4)
    const float4 qb = qv[32 + lane];     // query dims [128+4*lane, ...)

    const int j0 = s * 32 + w * 4;

    // Phase 1: 4 dot products with ILP, warp-local.
    const float4* r0 = (const float4*)(q_w + (size_t)(j0 + 0) * DZ);
    const float4* r1 = (const float4*)(q_w + (size_t)(j0 + 1) * DZ);
    const float4* r2 = (const float4*)(q_w + (size_t)(j0 + 2) * DZ);
    const float4* r3 = (const float4*)(q_w + (size_t)(j0 + 3) * DZ);
    const float4 a0 = r0[lane], b0 = r0[32 + lane];
    const float4 a1 = r1[lane], b1 = r1[32 + lane];
    const float4 a2 = r2[lane], b2 = r2[32 + lane];
    const float4 a3 = r3[lane], b3 = r3[32 + lane];
    float d0 = DOT8(a0, b0);
    float d1 = DOT8(a1, b1);
    float d2 = DOT8(a2, b2);
    float d3 = DOT8(a3, b3);
    #pragma unroll
    for (int o = 16; o > 0; o >>= 1) {
        d0 += __shfl_xor_sync(0xffffffffu, d0, o);
        d1 += __shfl_xor_sync(0xffffffffu, d1, o);
        d2 += __shfl_xor_sync(0xffffffffu, d2, o);
        d3 += __shfl_xor_sync(0xffffffffu, d3, o);
    }
    const float qr0 = d0 + __ldg(q_b + j0 + 0);
    const float qr1 = d1 + __ldg(q_b + j0 + 1);
    const float qr2 = d2 + __ldg(q_b + j0 + 2);
    const float qr3 = d3 + __ldg(q_b + j0 + 3);

    // Phase 2: partial qtil over the warp's 4 j, warp-local (no sync needed).
    const float4* k0 = (const float4*)(k_w + (size_t)(j0 + 0) * DZ);
    const float4* k1 = (const float4*)(k_w + (size_t)(j0 + 1) * DZ);
    const float4* k2 = (const float4*)(k_w + (size_t)(j0 + 2) * DZ);
    const float4* k3 = (const float4*)(k_w + (size_t)(j0 + 3) * DZ);
    const float4 w0a = k0[lane], w0b = k0[32 + lane];
    const float4 w1a = k1[lane], w1b = k1[32 + lane];
    const float4 w2a = k2[lane], w2b = k2[32 + lane];
    const float4 w3a = k3[lane], w3b = k3[32 + lane];

    float4 pa, pb;
    pa.x = qr0 * w0a.x + qr1 * w1a.x + qr2 * w2a.x + qr3 * w3a.x;
    pa.y = qr0 * w0a.y + qr1 * w1a.y + qr2 * w2a.y + qr3 * w3a.y;
    pa.z = qr0 * w0a.z + qr1 * w1a.z + qr2 * w2a.z + qr3 * w3a.z;
    pa.w = qr0 * w0a.w + qr1 * w1a.w + qr2 * w2a.w + qr3 * w3a.w;
    pb.x = qr0 * w0b.x + qr1 * w1b.x + qr2 * w2b.x + qr3 * w3b.x;
    pb.y = qr0 * w0b.y + qr1 * w1b.y + qr2 * w2b.y + qr3 * w3b.y;
    pb.z = qr0 * w0b.z + qr1 * w1b.z + qr2 * w2b.z + qr3 * w3b.z;
    pb.w = qr0 * w0b.w + qr1 * w1b.w + qr2 * w2b.w + qr3 * w3b.w;

    *(float4*)(&part[w][lane * 4])       = pa;
    *(float4*)(&part[w][128 + lane * 4]) = pb;
    __syncthreads();

    float acc = 0.0f;
    #pragma unroll
    for (int i = 0; i < WARPS; i++) acc += part[i][tid];
    g_part[(b * NSLICE + s) * DZ + tid] = acc;
}

// ---------------------------------------------------------------------------
// Kernel B: single streaming pass with online softmax.
// Prologue reduces the 8 qtil partials (L2-resident) in-block.
// Block = (batch, chunk), 1024 blocks. Warp owns 32 tokens, ILP groups of 4.
// ---------------------------------------------------------------------------
#define ONLINE_UPDATE(dt, xa, xb)                                          \
    do {                                                                   \
        float p;                                                           \
        if (dt > m) {                                                      \
            const float corr = __expf(m - dt);                             \
            z *= corr;                                                     \
            aa.x *= corr; aa.y *= corr; aa.z *= corr; aa.w *= corr;        \
            ab.x *= corr; ab.y *= corr; ab.z *= corr; ab.w *= corr;        \
            m = dt; p = 1.0f;                                              \
        } else {                                                           \
            p = __expf(dt - m);                                            \
        }                                                                  \
        z += p;                                                            \
        aa.x += p * (xa).x; aa.y += p * (xa).y;                            \
        aa.z += p * (xa).z; aa.w += p * (xa).w;                            \
        ab.x += p * (xb).x; ab.y += p * (xb).y;                            \
        ab.z += p * (xb).z; ab.w += p * (xb).w;                            \
    } while (0)

__global__ void __launch_bounds__(256) attn_pass(const float* __restrict__ tokens)
{
    const int b    = blockIdx.x >> 5;     // / NCHUNK
    const int c    = blockIdx.x & 31;     // % NCHUNK
    const int tid  = threadIdx.x;
    const int w    = tid >> 5;
    const int lane = tid & 31;

    __shared__ float qtil_s[DZ];

    // Fused reduction of qtil partials (8 coalesced L2 reads per thread).
    {
        const float* gp = g_part + (size_t)b * NSLICE * DZ + tid;
        float t = 0.0f;
        #pragma unroll
        for (int s2 = 0; s2 < NSLICE; s2++) t += gp[s2 * DZ];
        qtil_s[tid] = t * ATTN_SCALE;
    }
    __syncthreads();

    const float4 qa = *(const float4*)(qtil_s + lane * 4);
    const float4 qb = *(const float4*)(qtil_s + 128 + lane * 4);

    float  m = -1e30f, z = 0.0f;
    float4 aa = make_float4(0.f, 0.f, 0.f, 0.f);
    float4 ab = make_float4(0.f, 0.f, 0.f, 0.f);

    const int tok0 = c * TOKS + w * TOKS_PER_WARP;
    const float4* base = (const float4*)tokens + ((size_t)b * MZ + tok0) * (DZ / 4);

    #pragma unroll 2
    for (int g = 0; g < TOKS_PER_WARP / 4; g++) {
        const float4* tp = base + (size_t)g * 4 * (DZ / 4);
        const float4 xa0 = __ldcs(tp + lane);
        const float4 xb0 = __ldcs(tp + 32 + lane);
        const float4 xa1 = __ldcs(tp + 64 + lane);
        const float4 xb1 = __ldcs(tp + 96 + lane);
        const float4 xa2 = __ldcs(tp + 128 + lane);
        const float4 xb2 = __ldcs(tp + 160 + lane);
        const float4 xa3 = __ldcs(tp + 192 + lane);
        const float4 xb3 = __ldcs(tp + 224 + lane);

        float d0 = DOT8(xa0, xb0);
        float d1 = DOT8(xa1, xb1);
        float d2 = DOT8(xa2, xb2);
        float d3 = DOT8(xa3, xb3);
        #pragma unroll
        for (int o = 16; o > 0; o >>= 1) {
            d0 += __shfl_xor_sync(0xffffffffu, d0, o);
            d1 += __shfl_xor_sync(0xffffffffu, d1, o);
            d2 += __shfl_xor_sync(0xffffffffu, d2, o);
            d3 += __shfl_xor_sync(0xffffffffu, d3, o);
        }
        ONLINE_UPDATE(d0, xa0, xb0);
        ONLINE_UPDATE(d1, xa1, xb1);
        ONLINE_UPDATE(d2, xa2, xb2);
        ONLINE_UPDATE(d3, xa3, xb3);
    }

    // Combine 8 warps within the block
    __shared__ float  sm_m[WARPS];
    __shared__ float  sm_z[WARPS];
    __shared__ float4 sm_acc[WARPS][64];   // [warp][256 floats]

    if (lane == 0) { sm_m[w] = m; sm_z[w] = z; }
    sm_acc[w][lane]      = aa;
    sm_acc[w][32 + lane] = ab;
    __syncthreads();

    float Ms = sm_m[0];
    #pragma unroll
    for (int i = 1; i < WARPS; i++) Ms = fmaxf(Ms, sm_m[i]);

    const float* sa = (const float*)sm_acc;   // [8][256]
    float accd = 0.0f;
    #pragma unroll
    for (int i = 0; i < WARPS; i++)
        accd += sa[i * DZ + tid] * __expf(sm_m[i] - Ms);
    g_pacc[(b * NCHUNK + c) * DZ + tid] = accd;

    if (tid == 0) {
        float zt = 0.0f;
        #pragma unroll
        for (int i = 0; i < WARPS; i++) zt += sm_z[i] * __expf(sm_m[i] - Ms);
        g_pmz[b * NCHUNK + c] = make_float2(Ms, zt);
    }
}

// ---------------------------------------------------------------------------
// Kernel C: block (b,s), 256 blocks. Redundantly merge chunk partials ->
// t[b,:] (L2-resident), then compute 32 output dims: out[b,j] = v_w[j,:].t + v_b[j]
// ---------------------------------------------------------------------------
__global__ void __launch_bounds__(256) finalize(
    const float* __restrict__ v_w,
    const float* __restrict__ v_b,
    float* __restrict__ out)
{
    const int b    = blockIdx.x >> 3;
    const int s    = blockIdx.x & 7;
    const int tid  = threadIdx.x;
    const int w    = tid >> 5;
    const int lane = tid & 31;

    __shared__ float  t_s[DZ];
    __shared__ float2 mz_s[NCHUNK];

    if (tid < NCHUNK) mz_s[tid] = g_pmz[b * NCHUNK + tid];
    __syncthreads();

    float Mg = mz_s[0].x;
    #pragma unroll
    for (int i = 1; i < NCHUNK; i++) Mg = fmaxf(Mg, mz_s[i].x);

    float Zg = 0.0f;
    #pragma unroll
    for (int i = 0; i < NCHUNK; i++) Zg += mz_s[i].y * __expf(mz_s[i].x - Mg);
    const float inv = 1.0f / Zg;

    float td = 0.0f;
    #pragma unroll 8
    for (int i = 0; i < NCHUNK; i++)
        td += g_pacc[(b * NCHUNK + i) * DZ + tid] * __expf(mz_s[i].x - Mg);
    t_s[tid] = td * inv;
    __syncthreads();

    const float4 qa = *(const float4*)(t_s + lane * 4);
    const float4 qb = *(const float4*)(t_s + 128 + lane * 4);

    // Warp w computes outputs j in [32s + 4w, 32s + 4w + 4) with ILP.
    const int j0 = s * 32 + w * 4;
    const float4* r0 = (const float4*)(v_w + (size_t)(j0 + 0) * DZ);
    const float4* r1 = (const float4*)(v_w + (size_t)(j0 + 1) * DZ);
    const float4* r2 = (const float4*)(v_w + (size_t)(j0 + 2) * DZ);
    const float4* r3 = (const float4*)(v_w + (size_t)(j0 + 3) * DZ);
    const float4 a0 = r0[lane], b0 = r0[32 + lane];
    const float4 a1 = r1[lane], b1 = r1[32 + lane];
    const float4 a2 = r2[lane], b2 = r2[32 + lane];
    const float4 a3 = r3[lane], b3 = r3[32 + lane];
    float d0 = DOT8(a0, b0);
    float d1 = DOT8(a1, b1);
    float d2 = DOT8(a2, b2);
    float d3 = DOT8(a3, b3);
    #pragma unroll
    for (int o = 16; o > 0; o >>= 1) {
        d0 += __shfl_xor_sync(0xffffffffu, d0, o);
        d1 += __shfl_xor_sync(0xffffffffu, d1, o);
        d2 += __shfl_xor_sync(0xffffffffu, d2, o);
        d3 += __shfl_xor_sync(0xffffffffu, d3, o);
    }
    if (lane < 4) {
        const float v = (lane == 0) ? d0 : (lane == 1) ? d1 : (lane == 2) ? d2 : d3;
        out[b * DZ + j0 + lane] = v + __ldg(v_b + j0 + lane);
    }
}

// ---------------------------------------------------------------------------
// Inputs (metadata order): 0 query, 1 tokens, 2 q_w, 3 q_b, 4 k_w, 5 k_b,
//                          6 v_w, 7 v_b.  k_b is provably unused (softmax
//                          shift invariance).
// ---------------------------------------------------------------------------
extern "C" void kernel_launch(void* const* d_in, const int* in_sizes, int n_in,
                              void* d_out, int out_size)
{
    const float* query  = (const float*)d_in[0];
    const float* tokens = (const float*)d_in[1];
    const float* q_w    = (const float*)d_in[2];
    const float* q_b    = (const float*)d_in[3];
    const float* k_w    = (const float*)d_in[4];
    const float* v_w    = (const float*)d_in[6];
    const float* v_b    = (const float*)d_in[7];
    float* out = (float*)d_out;

    qtil_partial<<<BZ * NSLICE, 256>>>(query, q_w, q_b, k_w);
    attn_pass<<<BZ * NCHUNK, 256>>>(tokens);
    finalize<<<BZ * NSLICE, 256>>>(v_w, v_b, out);
}

// round 6
// speedup vs baseline: 3.0262x; 1.0006x over previous
#include <cuda_runtime.h>

#define BZ 32
#define MZ 8192
#define DZ 256
#define NCHUNK 32
#define TOKS (MZ / NCHUNK)            // 256 tokens per chunk
#define WARPS 8
#define TOKS_PER_WARP (TOKS / WARPS)  // 32
#define NSLICE 8                      // j-slices for kernels A and C
#define ATTN_SCALE 0.0625f            // 1/sqrt(256)

// Scratch (no allocations allowed in kernel_launch)
__device__ float  g_part[BZ * NSLICE * DZ];        // qtil partials, 256 KB
__device__ float  g_pacc[BZ * NCHUNK * DZ];        // 1 MB
__device__ float2 g_pmz[BZ * NCHUNK];              // (max, Z) per chunk

#define DOT8(xa, xb) ((xa).x*qa.x + (xa).y*qa.y + (xa).z*qa.z + (xa).w*qa.w \
                    + (xb).x*qb.x + (xb).y*qb.y + (xb).z*qb.z + (xb).w*qb.w)

// ---------------------------------------------------------------------------
// Kernel A: partial q~ per (batch, j-slice).  Block (b,s), 256 blocks.
// ---------------------------------------------------------------------------
__global__ void __launch_bounds__(256) qtil_partial(
    const float* __restrict__ query,
    const float* __restrict__ q_w,
    const float* __restrict__ q_b,
    const float* __restrict__ k_w)
{
    const int b    = blockIdx.x >> 3;
    const int s    = blockIdx.x & 7;
    const int tid  = threadIdx.x;
    const int w    = tid >> 5;
    const int lane = tid & 31;

    __shared__ float part[WARPS][DZ];   // 8 KB

    const float4* qv = (const float4*)(query + (size_t)b * DZ);
    const float4 qa = qv[lane];
    const float4 qb = qv[32 + lane];

    const int j0 = s * 32 + w * 4;

    // Phase 1: qr[j] = q_w[j,:].query[b] + q_b[j], 4 dots with ILP.
    const float4* r0 = (const float4*)(q_w + (size_t)(j0 + 0) * DZ);
    const float4* r1 = (const float4*)(q_w + (size_t)(j0 + 1) * DZ);
    const float4* r2 = (const float4*)(q_w + (size_t)(j0 + 2) * DZ);
    const float4* r3 = (const float4*)(q_w + (size_t)(j0 + 3) * DZ);
    const float4 a0 = r0[lane], b0 = r0[32 + lane];
    const float4 a1 = r1[lane], b1 = r1[32 + lane];
    const float4 a2 = r2[lane], b2 = r2[32 + lane];
    const float4 a3 = r3[lane], b3 = r3[32 + lane];
    float d0 = DOT8(a0, b0);
    float d1 = DOT8(a1, b1);
    float d2 = DOT8(a2, b2);
    float d3 = DOT8(a3, b3);
    #pragma unroll
    for (int o = 16; o > 0; o >>= 1) {
        d0 += __shfl_xor_sync(0xffffffffu, d0, o);
        d1 += __shfl_xor_sync(0xffffffffu, d1, o);
        d2 += __shfl_xor_sync(0xffffffffu, d2, o);
        d3 += __shfl_xor_sync(0xffffffffu, d3, o);
    }
    const float qr0 = d0 + __ldg(q_b + j0 + 0);
    const float qr1 = d1 + __ldg(q_b + j0 + 1);
    const float qr2 = d2 + __ldg(q_b + j0 + 2);
    const float qr3 = d3 + __ldg(q_b + j0 + 3);

    // Phase 2: partial qtil over the warp's 4 j (warp-local).
    const float4* k0 = (const float4*)(k_w + (size_t)(j0 + 0) * DZ);
    const float4* k1 = (const float4*)(k_w + (size_t)(j0 + 1) * DZ);
    const float4* k2 = (const float4*)(k_w + (size_t)(j0 + 2) * DZ);
    const float4* k3 = (const float4*)(k_w + (size_t)(j0 + 3) * DZ);
    const float4 w0a = k0[lane], w0b = k0[32 + lane];
    const float4 w1a = k1[lane], w1b = k1[32 + lane];
    const float4 w2a = k2[lane], w2b = k2[32 + lane];
    const float4 w3a = k3[lane], w3b = k3[32 + lane];

    float4 pa, pb;
    pa.x = qr0 * w0a.x + qr1 * w1a.x + qr2 * w2a.x + qr3 * w3a.x;
    pa.y = qr0 * w0a.y + qr1 * w1a.y + qr2 * w2a.y + qr3 * w3a.y;
    pa.z = qr0 * w0a.z + qr1 * w1a.z + qr2 * w2a.z + qr3 * w3a.z;
    pa.w = qr0 * w0a.w + qr1 * w1a.w + qr2 * w2a.w + qr3 * w3a.w;
    pb.x = qr0 * w0b.x + qr1 * w1b.x + qr2 * w2b.x + qr3 * w3b.x;
    pb.y = qr0 * w0b.y + qr1 * w1b.y + qr2 * w2b.y + qr3 * w3b.y;
    pb.z = qr0 * w0b.z + qr1 * w1b.z + qr2 * w2b.z + qr3 * w3b.z;
    pb.w = qr0 * w0b.w + qr1 * w1b.w + qr2 * w2b.w + qr3 * w3b.w;

    *(float4*)(&part[w][lane * 4])       = pa;
    *(float4*)(&part[w][128 + lane * 4]) = pb;
    __syncthreads();

    float acc = 0.0f;
    #pragma unroll
    for (int i = 0; i < WARPS; i++) acc += part[i][tid];
    g_part[(b * NSLICE + s) * DZ + tid] = acc;
}

// ---------------------------------------------------------------------------
// Kernel B: single streaming pass with online softmax.
// 8-token groups: 16 independent LDG.128 up front, interleaved shuffle
// reductions, ONE group-max rescale, 8 independent exp+accumulate chains.
// ---------------------------------------------------------------------------
#define ACC8(p, xa, xb)                                                    \
    do {                                                                   \
        aa.x += (p) * (xa).x; aa.y += (p) * (xa).y;                        \
        aa.z += (p) * (xa).z; aa.w += (p) * (xa).w;                        \
        ab.x += (p) * (xb).x; ab.y += (p) * (xb).y;                        \
        ab.z += (p) * (xb).z; ab.w += (p) * (xb).w;                        \
    } while (0)

__global__ void __launch_bounds__(256) attn_pass(const float* __restrict__ tokens)
{
    const int b    = blockIdx.x >> 5;     // / NCHUNK
    const int c    = blockIdx.x & 31;     // % NCHUNK
    const int tid  = threadIdx.x;
    const int w    = tid >> 5;
    const int lane = tid & 31;

    __shared__ float qtil_s[DZ];

    // Fused reduction of qtil partials (L2-resident).
    {
        const float* gp = g_part + (size_t)b * NSLICE * DZ + tid;
        float t = 0.0f;
        #pragma unroll
        for (int s2 = 0; s2 < NSLICE; s2++) t += gp[s2 * DZ];
        qtil_s[tid] = t * ATTN_SCALE;
    }
    __syncthreads();

    const float4 qa = *(const float4*)(qtil_s + lane * 4);
    const float4 qb = *(const float4*)(qtil_s + 128 + lane * 4);

    float  m = -1e30f, z = 0.0f;
    float4 aa = make_float4(0.f, 0.f, 0.f, 0.f);
    float4 ab = make_float4(0.f, 0.f, 0.f, 0.f);

    const int tok0 = c * TOKS + w * TOKS_PER_WARP;
    const float4* base = (const float4*)tokens + ((size_t)b * MZ + tok0) * (DZ / 4);

    for (int g = 0; g < TOKS_PER_WARP / 8; g++) {   // 4 iterations
        const float4* tp = base + (size_t)g * 8 * (DZ / 4);
        // 16 independent streaming loads (8 tokens x 2 float4)
        const float4 xa0 = __ldcs(tp + lane);
        const float4 xb0 = __ldcs(tp + 32 + lane);
        const float4 xa1 = __ldcs(tp + 64 + lane);
        const float4 xb1 = __ldcs(tp + 96 + lane);
        const float4 xa2 = __ldcs(tp + 128 + lane);
        const float4 xb2 = __ldcs(tp + 160 + lane);
        const float4 xa3 = __ldcs(tp + 192 + lane);
        const float4 xb3 = __ldcs(tp + 224 + lane);
        const float4 xa4 = __ldcs(tp + 256 + lane);
        const float4 xb4 = __ldcs(tp + 288 + lane);
        const float4 xa5 = __ldcs(tp + 320 + lane);
        const float4 xb5 = __ldcs(tp + 352 + lane);
        const float4 xa6 = __ldcs(tp + 384 + lane);
        const float4 xb6 = __ldcs(tp + 416 + lane);
        const float4 xa7 = __ldcs(tp + 448 + lane);
        const float4 xb7 = __ldcs(tp + 480 + lane);

        float d0 = DOT8(xa0, xb0);
        float d1 = DOT8(xa1, xb1);
        float d2 = DOT8(xa2, xb2);
        float d3 = DOT8(xa3, xb3);
        float d4 = DOT8(xa4, xb4);
        float d5 = DOT8(xa5, xb5);
        float d6 = DOT8(xa6, xb6);
        float d7 = DOT8(xa7, xb7);
        #pragma unroll
        for (int o = 16; o > 0; o >>= 1) {
            d0 += __shfl_xor_sync(0xffffffffu, d0, o);
            d1 += __shfl_xor_sync(0xffffffffu, d1, o);
            d2 += __shfl_xor_sync(0xffffffffu, d2, o);
            d3 += __shfl_xor_sync(0xffffffffu, d3, o);
            d4 += __shfl_xor_sync(0xffffffffu, d4, o);
            d5 += __shfl_xor_sync(0xffffffffu, d5, o);
            d6 += __shfl_xor_sync(0xffffffffu, d6, o);
            d7 += __shfl_xor_sync(0xffffffffu, d7, o);
        }

        // Single group-max rescale, then 8 independent exp+acc chains.
        float gm = fmaxf(fmaxf(fmaxf(d0, d1), fmaxf(d2, d3)),
                         fmaxf(fmaxf(d4, d5), fmaxf(d6, d7)));
        if (gm > m) {
            const float corr = __expf(m - gm);   // first group: exp(-inf)=0
            z *= corr;
            aa.x *= corr; aa.y *= corr; aa.z *= corr; aa.w *= corr;
            ab.x *= corr; ab.y *= corr; ab.z *= corr; ab.w *= corr;
            m = gm;
        }
        const float p0 = __expf(d0 - m);
        const float p1 = __expf(d1 - m);
        const float p2 = __expf(d2 - m);
        const float p3 = __expf(d3 - m);
        const float p4 = __expf(d4 - m);
        const float p5 = __expf(d5 - m);
        const float p6 = __expf(d6 - m);
        const float p7 = __expf(d7 - m);
        z += ((p0 + p1) + (p2 + p3)) + ((p4 + p5) + (p6 + p7));
        ACC8(p0, xa0, xb0);
        ACC8(p1, xa1, xb1);
        ACC8(p2, xa2, xb2);
        ACC8(p3, xa3, xb3);
        ACC8(p4, xa4, xb4);
        ACC8(p5, xa5, xb5);
        ACC8(p6, xa6, xb6);
        ACC8(p7, xa7, xb7);
    }

    // Combine 8 warps within the block
    __shared__ float  sm_m[WARPS];
    __shared__ float  sm_z[WARPS];
    __shared__ float4 sm_acc[WARPS][64];   // [warp][256 floats]

    if (lane == 0) { sm_m[w] = m; sm_z[w] = z; }
    sm_acc[w][lane]      = aa;
    sm_acc[w][32 + lane] = ab;
    __syncthreads();

    float Ms = sm_m[0];
    #pragma unroll
    for (int i = 1; i < WARPS; i++) Ms = fmaxf(Ms, sm_m[i]);

    const float* sa = (const float*)sm_acc;   // [8][256]
    float accd = 0.0f;
    #pragma unroll
    for (int i = 0; i < WARPS; i++)
        accd += sa[i * DZ + tid] * __expf(sm_m[i] - Ms);
    g_pacc[(b * NCHUNK + c) * DZ + tid] = accd;

    if (tid == 0) {
        float zt = 0.0f;
        #pragma unroll
        for (int i = 0; i < WARPS; i++) zt += sm_z[i] * __expf(sm_m[i] - Ms);
        g_pmz[b * NCHUNK + c] = make_float2(Ms, zt);
    }
}

// ---------------------------------------------------------------------------
// Kernel C: block (b,s), 256 blocks. Merge chunk partials -> t[b,:] (L2-
// resident), then 32 output dims: out[b,j] = v_w[j,:].t + v_b[j]
// ---------------------------------------------------------------------------
__global__ void __launch_bounds__(256) finalize(
    const float* __restrict__ v_w,
    const float* __restrict__ v_b,
    float* __restrict__ out)
{
    const int b    = blockIdx.x >> 3;
    const int s    = blockIdx.x & 7;
    const int tid  = threadIdx.x;
    const int w    = tid >> 5;
    const int lane = tid & 31;

    __shared__ float  t_s[DZ];
    __shared__ float2 mz_s[NCHUNK];

    if (tid < NCHUNK) mz_s[tid] = g_pmz[b * NCHUNK + tid];
    __syncthreads();

    float Mg = mz_s[0].x;
    #pragma unroll
    for (int i = 1; i < NCHUNK; i++) Mg = fmaxf(Mg, mz_s[i].x);

    float Zg = 0.0f;
    #pragma unroll
    for (int i = 0; i < NCHUNK; i++) Zg += mz_s[i].y * __expf(mz_s[i].x - Mg);
    const float inv = 1.0f / Zg;

    float td = 0.0f;
    #pragma unroll 8
    for (int i = 0; i < NCHUNK; i++)
        td += g_pacc[(b * NCHUNK + i) * DZ + tid] * __expf(mz_s[i].x - Mg);
    t_s[tid] = td * inv;
    __syncthreads();

    const float4 qa = *(const float4*)(t_s + lane * 4);
    const float4 qb = *(const float4*)(t_s + 128 + lane * 4);

    const int j0 = s * 32 + w * 4;
    const float4* r0 = (const float4*)(v_w + (size_t)(j0 + 0) * DZ);
    const float4* r1 = (const float4*)(v_w + (size_t)(j0 + 1) * DZ);
    const float4* r2 = (const float4*)(v_w + (size_t)(j0 + 2) * DZ);
    const float4* r3 = (const float4*)(v_w + (size_t)(j0 + 3) * DZ);
    const float4 a0 = r0[lane], b0 = r0[32 + lane];
    const float4 a1 = r1[lane], b1 = r1[32 + lane];
    const float4 a2 = r2[lane], b2 = r2[32 + lane];
    const float4 a3 = r3[lane], b3 = r3[32 + lane];
    float d0 = DOT8(a0, b0);
    float d1 = DOT8(a1, b1);
    float d2 = DOT8(a2, b2);
    float d3 = DOT8(a3, b3);
    #pragma unroll
    for (int o = 16; o > 0; o >>= 1) {
        d0 += __shfl_xor_sync(0xffffffffu, d0, o);
        d1 += __shfl_xor_sync(0xffffffffu, d1, o);
        d2 += __shfl_xor_sync(0xffffffffu, d2, o);
        d3 += __shfl_xor_sync(0xffffffffu, d3, o);
    }
    if (lane < 4) {
        const float v = (lane == 0) ? d0 : (lane == 1) ? d1 : (lane == 2) ? d2 : d3;
        out[b * DZ + j0 + lane] = v + __ldg(v_b + j0 + lane);
    }
}

// ---------------------------------------------------------------------------
// Inputs (metadata order): 0 query, 1 tokens, 2 q_w, 3 q_b, 4 k_w, 5 k_b,
//                          6 v_w, 7 v_b.  k_b is provably unused (softmax
//                          shift invariance).
// ---------------------------------------------------------------------------
extern "C" void kernel_launch(void* const* d_in, const int* in_sizes, int n_in,
                              void* d_out, int out_size)
{
    const float* query  = (const float*)d_in[0];
    const float* tokens = (const float*)d_in[1];
    const float* q_w    = (const float*)d_in[2];
    const float* q_b    = (const float*)d_in[3];
    const float* k_w    = (const float*)d_in[4];
    const float* v_w    = (const float*)d_in[6];
    const float* v_b    = (const float*)d_in[7];
    float* out = (float*)d_out;

    qtil_partial<<<BZ * NSLICE, 256>>>(query, q_w, q_b, k_w);
    attn_pass<<<BZ * NCHUNK, 256>>>(tokens);
    finalize<<<BZ * NSLICE, 256>>>(v_w, v_b, out);
}